// round 5
// baseline (speedup 1.0000x reference)
#include <cuda_runtime.h>
#include <cstdint>

#define NN 50000
#define EE 600000
#define DD 128
#define HH 8
#define SCALE 0.25f   // (128/8)^-0.5

// ---------------- scratch (static device allocations; no cudaMalloc) ----------
__device__ __align__(16) float g_q[(size_t)NN * DD];
__device__ __align__(16) float g_k[(size_t)NN * DD];
__device__ __align__(16) float g_v[(size_t)NN * DD];
__device__ __align__(16) float g_acc[(size_t)NN * DD];
__device__ __align__(16) float g_G[(size_t)NN * 512];   // per-node, per-head We-projected q
__device__ float g_c[(size_t)NN * HH];                  // q . be per head
__device__ int   g_cnt[NN];
__device__ int   g_off[NN + 1];
__device__ int   g_cur[NN];
__device__ int2  g_sedge[EE];                           // (src, eid) sorted by dst

// ---------------- packed f32x2 helpers ----------------------------------------
__device__ __forceinline__ uint64_t pack2(float x, float y) {
    uint64_t r; asm("mov.b64 %0, {%1, %2};" : "=l"(r) : "f"(x), "f"(y)); return r;
}
__device__ __forceinline__ void ffma2(uint64_t& acc, uint64_t a, uint64_t b) {
    asm("fma.rn.f32x2 %0, %1, %2, %0;" : "+l"(acc) : "l"(a), "l"(b));
}
__device__ __forceinline__ float2 unpack2(uint64_t v) {
    float2 r; asm("mov.b64 {%0, %1}, %2;" : "=f"(r.x), "=f"(r.y) : "l"(v)); return r;
}

// ---------------- GEMM: C[M,128] = A[M,128] @ W[128,128] + b ------------------
// BM=64, BN=128, BK=16; 256 threads; 8x4 micro-tile via 4x4 packed f32x2 accum.
__global__ void __launch_bounds__(256) k_gemm128(
    const float* __restrict__ A, const float* __restrict__ W,
    const float* __restrict__ bias, float* __restrict__ C, int M)
{
    __shared__ float sA[16][64];
    __shared__ float sW[16][128];
    int tid = threadIdx.x;
    int tx = tid & 31;
    int ty = tid >> 5;
    int row0 = blockIdx.x * 64;

    uint64_t acc2[4][4];   // [row-pair][col]; .x = row 2ip, .y = row 2ip+1
#pragma unroll
    for (int i = 0; i < 4; i++)
#pragma unroll
        for (int j = 0; j < 4; j++) acc2[i][j] = pack2(0.f, 0.f);

    for (int k0 = 0; k0 < 128; k0 += 16) {
        {
            int m = tid >> 2, q = tid & 3;
            float4 a = make_float4(0.f, 0.f, 0.f, 0.f);
            if (row0 + m < M)
                a = *(const float4*)(A + (size_t)(row0 + m) * 128 + k0 + q * 4);
            sA[q * 4 + 0][m] = a.x;
            sA[q * 4 + 1][m] = a.y;
            sA[q * 4 + 2][m] = a.z;
            sA[q * 4 + 3][m] = a.w;
        }
#pragma unroll
        for (int i = 0; i < 2; i++) {
            int idx = tid + i * 256;
            int r = idx >> 5, c4 = idx & 31;
            *(float4*)&sW[r][c4 * 4] =
                *(const float4*)(W + (size_t)(k0 + r) * 128 + c4 * 4);
        }
        __syncthreads();
#pragma unroll
        for (int k = 0; k < 16; k++) {
            float4 w = *(float4*)&sW[k][tx * 4];
            uint64_t w2[4];
            w2[0] = pack2(w.x, w.x);
            w2[1] = pack2(w.y, w.y);
            w2[2] = pack2(w.z, w.z);
            w2[3] = pack2(w.w, w.w);
            float4 alo = *(float4*)&sA[k][ty * 8];
            float4 ahi = *(float4*)&sA[k][ty * 8 + 4];
            uint64_t a2[4];
            a2[0] = pack2(alo.x, alo.y);
            a2[1] = pack2(alo.z, alo.w);
            a2[2] = pack2(ahi.x, ahi.y);
            a2[3] = pack2(ahi.z, ahi.w);
#pragma unroll
            for (int ip = 0; ip < 4; ip++)
#pragma unroll
                for (int j = 0; j < 4; j++)
                    ffma2(acc2[ip][j], a2[ip], w2[j]);
        }
        __syncthreads();
    }

    float4 b4 = *(const float4*)(bias + tx * 4);
#pragma unroll
    for (int ip = 0; ip < 4; ip++) {
        float2 c0 = unpack2(acc2[ip][0]);
        float2 c1 = unpack2(acc2[ip][1]);
        float2 c2 = unpack2(acc2[ip][2]);
        float2 c3 = unpack2(acc2[ip][3]);
        int m0 = row0 + ty * 8 + ip * 2;
        if (m0 < M) {
            float4 o = make_float4(c0.x + b4.x, c1.x + b4.y, c2.x + b4.z, c3.x + b4.w);
            *(float4*)(C + (size_t)m0 * 128 + tx * 4) = o;
        }
        if (m0 + 1 < M) {
            float4 o = make_float4(c0.y + b4.x, c1.y + b4.y, c2.y + b4.z, c3.y + b4.w);
            *(float4*)(C + (size_t)(m0 + 1) * 128 + tx * 4) = o;
        }
    }
}

// ---------------- G transform -------------------------------------------------
// G[n,h,j] = sum_{i<16} q[n, 16h+i] * We[j, 16h+i]   (j in [0,64))
// c[n,h]   = sum_{i<16} q[n, 16h+i] * be[16h+i]
__global__ void __launch_bounds__(256) k_G(
    const float* __restrict__ We, const float* __restrict__ be, int N)
{
    int b = blockIdx.x;
    int h = b & 7;
    int n0 = (b >> 3) * 64;
    __shared__ float sQ[16][68];
    __shared__ float sW[16][68];
    __shared__ float sbe[16];
    int t = threadIdx.x;

    {
        int node = t & 63, ib = t >> 6;
        float4 v = make_float4(0.f, 0.f, 0.f, 0.f);
        if (n0 + node < N)
            v = *(const float4*)(g_q + (size_t)(n0 + node) * 128 + h * 16 + ib * 4);
        sQ[ib * 4 + 0][node] = v.x;
        sQ[ib * 4 + 1][node] = v.y;
        sQ[ib * 4 + 2][node] = v.z;
        sQ[ib * 4 + 3][node] = v.w;

        int j = node;
        float4 w = *(const float4*)(We + (size_t)j * 128 + h * 16 + ib * 4);
        sW[ib * 4 + 0][j] = w.x;
        sW[ib * 4 + 1][j] = w.y;
        sW[ib * 4 + 2][j] = w.z;
        sW[ib * 4 + 3][j] = w.w;
    }
    if (t < 16) sbe[t] = be[h * 16 + t];
    __syncthreads();

    int tn = t >> 4, tj = t & 15;
    float acc[4][4];
#pragma unroll
    for (int r = 0; r < 4; r++)
#pragma unroll
        for (int s = 0; s < 4; s++) acc[r][s] = 0.f;

#pragma unroll
    for (int i = 0; i < 16; i++) {
        float qv[4], wv[4];
#pragma unroll
        for (int r = 0; r < 4; r++) qv[r] = sQ[i][tn * 4 + r];
#pragma unroll
        for (int s = 0; s < 4; s++) wv[s] = sW[i][tj * 4 + s];
#pragma unroll
        for (int r = 0; r < 4; r++)
#pragma unroll
            for (int s = 0; s < 4; s++) acc[r][s] += qv[r] * wv[s];
    }

#pragma unroll
    for (int r = 0; r < 4; r++) {
        int n = n0 + tn * 4 + r;
        if (n < N) {
            float4 o = make_float4(acc[r][0], acc[r][1], acc[r][2], acc[r][3]);
            *(float4*)(g_G + (size_t)n * 512 + h * 64 + tj * 4) = o;
        }
    }

    if (t < 64) {
        int n = n0 + t;
        if (n < N) {
            float s = 0.f;
#pragma unroll
            for (int i = 0; i < 16; i++) s += sQ[i][t] * sbe[i];
            g_c[(size_t)n * 8 + h] = s;
        }
    }
}

// ---------------- counting sort by dst ----------------------------------------
__global__ void k_zero_cnt(int N) {
    int i = blockIdx.x * blockDim.x + threadIdx.x;
    if (i < N) g_cnt[i] = 0;
}

__global__ void k_hist(const int* __restrict__ ei, int E) {
    int i = blockIdx.x * blockDim.x + threadIdx.x;
    if (i < E) atomicAdd(&g_cnt[ei[E + i]], 1);
}

__global__ void __launch_bounds__(1024) k_scan(int N) {
    __shared__ int s_sums[1024];
    int t = threadIdx.x;
    int chunk = (N + 1023) / 1024;
    int beg = t * chunk;
    int end = min(beg + chunk, N);
    int s = 0;
    for (int i = beg; i < end; i++) s += g_cnt[i];
    s_sums[t] = s;
    __syncthreads();
    for (int d = 1; d < 1024; d <<= 1) {
        int v = (t >= d) ? s_sums[t - d] : 0;
        __syncthreads();
        s_sums[t] += v;
        __syncthreads();
    }
    int run = (t == 0) ? 0 : s_sums[t - 1];
    for (int i = beg; i < end; i++) {
        int c = g_cnt[i];
        g_off[i] = run;
        g_cur[i] = run;
        run += c;
    }
    if (t == 1023) g_off[N] = s_sums[1023];
}

__global__ void k_scatter(const int* __restrict__ ei, int E) {
    int i = blockIdx.x * blockDim.x + threadIdx.x;
    if (i >= E) return;
    int dst = ei[E + i];
    int pos = atomicAdd(&g_cur[dst], 1);
    g_sedge[pos] = make_int2(ei[i], i);
}

// ---------------- fused attention: one warp per destination node --------------
// Single pass: acc += exp(logit) * v[src]; denom in registers; normalize at end.
__global__ void __launch_bounds__(256) k_attn(
    const float* __restrict__ ea, int N)
{
    __shared__ __align__(16) float sEa[8][64];
    int lane = threadIdx.x & 31;
    int w = threadIdx.x >> 5;
    int dst = blockIdx.x * 8 + w;
    if (dst >= N) return;

    int h = lane >> 2, p = lane & 3;
    int beg = g_off[dst], end = g_off[dst + 1];

    const float4* q4 = (const float4*)g_q;
    const float4* k4 = (const float4*)g_k;
    const float4* v4 = (const float4*)g_v;

    float4 qv = q4[(size_t)dst * 32 + lane];
    float4 Gr[4];
    {
        const float4* Gp = (const float4*)(g_G + (size_t)dst * 512 + h * 64 + p * 16);
#pragma unroll
        for (int i = 0; i < 4; i++) Gr[i] = Gp[i];
    }
    float cc = g_c[(size_t)dst * 8 + h];

    float denom = 0.f;
    float4 acc = make_float4(0.f, 0.f, 0.f, 0.f);

    for (int e = beg; e < end; e++) {
        int2 se = g_sedge[e];
        float4 kv = k4[(size_t)se.x * 32 + lane];
        float4 vv = v4[(size_t)se.x * 32 + lane];
        ((float2*)sEa[w])[lane] = ((const float2*)(ea + (size_t)se.y * 64))[lane];
        __syncwarp();

        float t = qv.x * kv.x + qv.y * kv.y + qv.z * kv.z + qv.w * kv.w;
        const float4* ap = (const float4*)sEa[w] + p * 4;
#pragma unroll
        for (int i = 0; i < 4; i++) {
            float4 av = ap[i];
            t += av.x * Gr[i].x + av.y * Gr[i].y + av.z * Gr[i].z + av.w * Gr[i].w;
        }
        t += __shfl_down_sync(0xffffffffu, t, 1);
        t += __shfl_down_sync(0xffffffffu, t, 2);

        float exv = 0.f;
        if (p == 0) {
            exv = __expf((t + cc) * SCALE);
            denom += exv;
        }
        exv = __shfl_sync(0xffffffffu, exv, lane & ~3);
        acc.x += exv * vv.x;
        acc.y += exv * vv.y;
        acc.z += exv * vv.z;
        acc.w += exv * vv.w;
        __syncwarp();
    }

    float inv = (p == 0 && denom != 0.f) ? (1.f / denom) : 0.f;
    inv = __shfl_sync(0xffffffffu, inv, lane & ~3);
    acc.x *= inv; acc.y *= inv; acc.z *= inv; acc.w *= inv;
    *(float4*)(g_acc + (size_t)dst * 128 + lane * 4) = acc;
}

// ---------------- launch ------------------------------------------------------
extern "C" void kernel_launch(void* const* d_in, const int* in_sizes, int n_in,
                              void* d_out, int out_size)
{
    const float* x  = (const float*)d_in[0];
    const float* ea = (const float*)d_in[1];
    const float* Wq = (const float*)d_in[2];
    const float* bq = (const float*)d_in[3];
    const float* Wk = (const float*)d_in[4];
    const float* bk = (const float*)d_in[5];
    const float* Wv = (const float*)d_in[6];
    const float* bv = (const float*)d_in[7];
    const float* We = (const float*)d_in[8];
    const float* be = (const float*)d_in[9];
    const float* Wo = (const float*)d_in[10];
    const float* bo = (const float*)d_in[11];
    const int*   ei = (const int*)d_in[12];

    int N = in_sizes[0] / DD;
    int E = in_sizes[12] / 2;

    float* qp;   cudaGetSymbolAddress((void**)&qp,   g_q);
    float* kp;   cudaGetSymbolAddress((void**)&kp,   g_k);
    float* vp;   cudaGetSymbolAddress((void**)&vp,   g_v);
    float* accp; cudaGetSymbolAddress((void**)&accp, g_acc);

    // sort edges by dst
    k_zero_cnt<<<(N + 255) / 256, 256>>>(N);
    k_hist<<<(E + 255) / 256, 256>>>(ei, E);
    k_scan<<<1, 1024>>>(N);
    k_scatter<<<(E + 255) / 256, 256>>>(ei, E);

    int gb = (N + 63) / 64;
    k_gemm128<<<gb, 256>>>(x, Wq, bq, qp, N);
    k_gemm128<<<gb, 256>>>(x, Wk, bk, kp, N);
    k_gemm128<<<gb, 256>>>(x, Wv, bv, vp, N);

    k_G<<<gb * 8, 256>>>(We, be, N);

    k_attn<<<(N + 7) / 8, 256>>>(ea, N);

    k_gemm128<<<gb, 256>>>(accp, Wo, bo, (float*)d_out, N);
}